// round 16
// baseline (speedup 1.0000x reference)
#include <cuda_runtime.h>
#include <math.h>
#include <stdint.h>

// Problem constants
namespace cfg {
constexpr int B = 2, S = 1024, H = 2048;
constexpr int NH = 16, NKV = 8, HD = 128;
constexpr int GROUPS = NH / NKV;       // 2
constexpr int TOPK = 409;              // int(0.4 * 1024)
constexpr int MSZ = B * S;             // 2048
constexpr int QN = NH * HD;            // 2048
constexpr int KN = NKV * HD;           // 1024
// attention tiling
constexpr int QT = 8;
constexpr int RR = QT * GROUPS;        // 16
constexpr int TK = 64;
constexpr int NT = S / TK;             // 16
constexpr int KPAD = 132;              // K/V tile row stride (floats)
constexpr int SPAD = 1028;             // ps/su row stride (floats)
}

// Scratch
__device__ float g_q[(size_t)cfg::MSZ * cfg::QN];
__device__ float g_k[(size_t)cfg::MSZ * cfg::KN];
__device__ float g_v[(size_t)cfg::MSZ * cfg::KN];
__device__ float g_attn[(size_t)cfg::MSZ * cfg::QN];

// ---------------------------------------------------------------------------
// Packed dual-fp32 FMA (bitwise identical to two fmaf calls)
// ---------------------------------------------------------------------------
typedef unsigned long long u64;
__device__ __forceinline__ u64 pack2(float lo, float hi) {
    u64 r;
    asm("mov.b64 %0, {%1, %2};" : "=l"(r) : "f"(lo), "f"(hi));
    return r;
}
__device__ __forceinline__ void fma2(u64& d, u64 a, u64 b) {
    asm("fma.rn.f32x2 %0, %1, %2, %0;" : "+l"(d) : "l"(a), "l"(b));
}
__device__ __forceinline__ float2 unpack2(u64 v) {
    float2 r;
    asm("mov.b64 {%0, %1}, %2;" : "=f"(r.x), "=f"(r.y) : "l"(v));
    return r;
}

// ---------------------------------------------------------------------------
// Tensor helpers
// ---------------------------------------------------------------------------
__device__ __forceinline__ float tf32_rna(float x) {
    float r;
    asm("cvt.rna.tf32.f32 %0, %1;" : "=f"(r) : "f"(x));
    return r;
}
__device__ __forceinline__ void mma_tf32(float* c, const uint32_t* a,
                                         uint32_t b0, uint32_t b1) {
    asm volatile(
        "mma.sync.aligned.m16n8k8.row.col.f32.tf32.tf32.f32 "
        "{%0,%1,%2,%3}, {%4,%5,%6,%7}, {%8,%9}, {%0,%1,%2,%3};"
        : "+f"(c[0]), "+f"(c[1]), "+f"(c[2]), "+f"(c[3])
        : "r"(a[0]), "r"(a[1]), "r"(a[2]), "r"(a[3]), "r"(b0), "r"(b1));
}

// ---------------------------------------------------------------------------
// SIMT fp32 GEMM body (double-buffered, FFMA2). Per-output FMA chain
// identical to R2..R15 -> bitwise identical results. Smem comes from caller.
// ---------------------------------------------------------------------------
__device__ __forceinline__ void simt_gemm_body(
    float* dsm, const float* __restrict__ A, const float* __restrict__ Bm,
    const float* __restrict__ bias, float* __restrict__ C, int N, int K)
{
    float* As = dsm;
    float* Bs = dsm + 4096;
    const int tid = threadIdx.x;
    const int bm = blockIdx.y * 128;
    const int bn = blockIdx.x * 128;
    const int tm = (tid >> 4) << 3;
    const int tn = (tid & 15) << 3;
    const int lr = tid >> 2;
    const int lc = (tid & 3) << 2;

    u64 acc2[8][4];
#pragma unroll
    for (int i = 0; i < 8; i++)
#pragma unroll
        for (int j = 0; j < 4; j++) acc2[i][j] = 0ull;

    const float* Ap = A + (size_t)(bm + lr) * K + lc;
    const float* Bp = Bm + (size_t)(bn + lr) * K + lc;

    float4 a0, a1, b0, b1;
    auto ldg = [&](int k0) {
        a0 = *(const float4*)(Ap + k0);
        a1 = *(const float4*)(Ap + (size_t)64 * K + k0);
        b0 = *(const float4*)(Bp + k0);
        b1 = *(const float4*)(Bp + (size_t)64 * K + k0);
    };
    auto sts = [&](int s) {
        float* as = As + s * 2048;
        float* bs = Bs + s * 2048;
        as[(lc + 0) * 128 + lr]      = a0.x; as[(lc + 1) * 128 + lr]      = a0.y;
        as[(lc + 2) * 128 + lr]      = a0.z; as[(lc + 3) * 128 + lr]      = a0.w;
        as[(lc + 0) * 128 + lr + 64] = a1.x; as[(lc + 1) * 128 + lr + 64] = a1.y;
        as[(lc + 2) * 128 + lr + 64] = a1.z; as[(lc + 3) * 128 + lr + 64] = a1.w;
        bs[(lc + 0) * 128 + lr]      = b0.x; bs[(lc + 1) * 128 + lr]      = b0.y;
        bs[(lc + 2) * 128 + lr]      = b0.z; bs[(lc + 3) * 128 + lr]      = b0.w;
        bs[(lc + 0) * 128 + lr + 64] = b1.x; bs[(lc + 1) * 128 + lr + 64] = b1.y;
        bs[(lc + 2) * 128 + lr + 64] = b1.z; bs[(lc + 3) * 128 + lr + 64] = b1.w;
    };

    ldg(0);
    sts(0);
    __syncthreads();

#pragma unroll 1
    for (int k0 = 0; k0 < K; k0 += 16) {
        const int cur = (k0 >> 4) & 1;
        if (k0 + 16 < K) ldg(k0 + 16);
        const float* as = As + cur * 2048;
        const float* bs = Bs + cur * 2048;
#pragma unroll
        for (int kk = 0; kk < 16; kk++) {
            float4 a40 = *(const float4*)&as[kk * 128 + tm];
            float4 a41 = *(const float4*)&as[kk * 128 + tm + 4];
            float4 b40 = *(const float4*)&bs[kk * 128 + tn];
            float4 b41 = *(const float4*)&bs[kk * 128 + tn + 4];
            float av[8] = {a40.x, a40.y, a40.z, a40.w, a41.x, a41.y, a41.z, a41.w};
            u64 bp[4] = {pack2(b40.x, b40.y), pack2(b40.z, b40.w),
                         pack2(b41.x, b41.y), pack2(b41.z, b41.w)};
#pragma unroll
            for (int i = 0; i < 8; i++) {
                u64 ai = pack2(av[i], av[i]);
#pragma unroll
                for (int j = 0; j < 4; j++)
                    fma2(acc2[i][j], ai, bp[j]);
            }
        }
        if (k0 + 16 < K) sts(cur ^ 1);
        __syncthreads();
    }

    float bvv[8];
#pragma unroll
    for (int j = 0; j < 8; j++) bvv[j] = bias[bn + tn + j];
#pragma unroll
    for (int i = 0; i < 8; i++) {
        float* Cp = C + (size_t)(bm + tm + i) * N + bn + tn;
#pragma unroll
        for (int j = 0; j < 4; j++) {
            float2 p = unpack2(acc2[i][j]);
            Cp[2 * j]     = p.x + bvv[2 * j];
            Cp[2 * j + 1] = p.y + bvv[2 * j + 1];
        }
    }
}

// ---------------------------------------------------------------------------
// 3-term TF32 GEMM body (smooth path). Smem from caller (needs 81920 B).
// ---------------------------------------------------------------------------
namespace tc {
constexpr int BM = 128, BN = 128, BK = 16;
constexpr int PAD = 20;
constexpr int TSZ = BM * PAD;
constexpr int STAGE = 4 * TSZ;
constexpr int SMEM_TOTAL = 2 * STAGE * 4;  // 81920 bytes
}

__device__ __forceinline__ void mma_gemm_body(
    float* sm, const float* __restrict__ A, const float* __restrict__ Bm,
    const float* __restrict__ bias, float* __restrict__ C, int N, int K)
{
    const int tid = threadIdx.x;
    const int lane = tid & 31, wid = tid >> 5;
    const int bm = blockIdx.y * tc::BM;
    const int bn = blockIdx.x * tc::BN;
    const int m0 = (wid & 3) * 32;
    const int n0 = (wid >> 2) * 64;

    float acc[2][8][4];
#pragma unroll
    for (int i = 0; i < 2; i++)
#pragma unroll
        for (int j = 0; j < 8; j++)
#pragma unroll
            for (int t = 0; t < 4; t++) acc[i][j][t] = 0.f;

    const int lrow = tid >> 2;
    const int lc4 = (tid & 3) * 4;
    float4 ra0, ra1, rb0, rb1;

    auto ldregs = [&](int kt) {
        const int k0 = kt * tc::BK;
        ra0 = *(const float4*)(A + (size_t)(bm + lrow) * K + k0 + lc4);
        ra1 = *(const float4*)(A + (size_t)(bm + lrow + 64) * K + k0 + lc4);
        rb0 = *(const float4*)(Bm + (size_t)(bn + lrow) * K + k0 + lc4);
        rb1 = *(const float4*)(Bm + (size_t)(bn + lrow + 64) * K + k0 + lc4);
    };
    auto split_store = [&](float* hi, float* lo, int row, float4 x) {
        float4 h, l;
        h.x = tf32_rna(x.x); l.x = tf32_rna(x.x - h.x);
        h.y = tf32_rna(x.y); l.y = tf32_rna(x.y - h.y);
        h.z = tf32_rna(x.z); l.z = tf32_rna(x.z - h.z);
        h.w = tf32_rna(x.w); l.w = tf32_rna(x.w - h.w);
        *(float4*)(hi + row * tc::PAD + lc4) = h;
        *(float4*)(lo + row * tc::PAD + lc4) = l;
    };
    auto stregs = [&](int s) {
        float* base = sm + s * tc::STAGE;
        split_store(base,               base + tc::TSZ,     lrow,      ra0);
        split_store(base,               base + tc::TSZ,     lrow + 64, ra1);
        split_store(base + 2 * tc::TSZ, base + 3 * tc::TSZ, lrow,      rb0);
        split_store(base + 2 * tc::TSZ, base + 3 * tc::TSZ, lrow + 64, rb1);
    };

    auto mma_stage = [&](int s) {
        const float* Ahi = sm + s * tc::STAGE;
        const float* Alo = Ahi + tc::TSZ;
        const float* Bhi = Ahi + 2 * tc::TSZ;
        const float* Blo = Ahi + 3 * tc::TSZ;
        const int lr4 = lane >> 2, lk = lane & 3;
#pragma unroll
        for (int ks = 0; ks < 2; ks++) {
            const int kb = ks * 8 + lk;
            uint32_t ah[2][4], al[2][4];
#pragma unroll
            for (int fm = 0; fm < 2; fm++) {
                const int mr = m0 + 16 * fm + lr4;
                ah[fm][0] = __float_as_uint(Ahi[mr * tc::PAD + kb]);
                ah[fm][1] = __float_as_uint(Ahi[(mr + 8) * tc::PAD + kb]);
                ah[fm][2] = __float_as_uint(Ahi[mr * tc::PAD + kb + 4]);
                ah[fm][3] = __float_as_uint(Ahi[(mr + 8) * tc::PAD + kb + 4]);
                al[fm][0] = __float_as_uint(Alo[mr * tc::PAD + kb]);
                al[fm][1] = __float_as_uint(Alo[(mr + 8) * tc::PAD + kb]);
                al[fm][2] = __float_as_uint(Alo[mr * tc::PAD + kb + 4]);
                al[fm][3] = __float_as_uint(Alo[(mr + 8) * tc::PAD + kb + 4]);
            }
#pragma unroll
            for (int fn = 0; fn < 8; fn++) {
                const int nr = n0 + 8 * fn + lr4;
                uint32_t bh0 = __float_as_uint(Bhi[nr * tc::PAD + kb]);
                uint32_t bh1 = __float_as_uint(Bhi[nr * tc::PAD + kb + 4]);
                uint32_t bl0 = __float_as_uint(Blo[nr * tc::PAD + kb]);
                uint32_t bl1 = __float_as_uint(Blo[nr * tc::PAD + kb + 4]);
#pragma unroll
                for (int fm = 0; fm < 2; fm++) {
                    mma_tf32(acc[fm][fn], ah[fm], bh0, bh1);
                    mma_tf32(acc[fm][fn], ah[fm], bl0, bl1);
                    mma_tf32(acc[fm][fn], al[fm], bh0, bh1);
                }
            }
        }
    };

    const int NK = K / tc::BK;
    ldregs(0);
    stregs(0);
    __syncthreads();
#pragma unroll 1
    for (int kt = 0; kt < NK; kt++) {
        const int cur = kt & 1;
        if (kt + 1 < NK) ldregs(kt + 1);
        mma_stage(cur);
        if (kt + 1 < NK) stregs(cur ^ 1);
        __syncthreads();
    }

    const int lr4 = lane >> 2, lc2 = 2 * (lane & 3);
#pragma unroll
    for (int fm = 0; fm < 2; fm++) {
#pragma unroll
        for (int fn = 0; fn < 8; fn++) {
            const int r = bm + m0 + 16 * fm + lr4;
            const int c = bn + n0 + 8 * fn + lc2;
            const float b0 = bias[c], b1 = bias[c + 1];
            float2 o0 = make_float2(acc[fm][fn][0] + b0, acc[fm][fn][1] + b1);
            float2 o1 = make_float2(acc[fm][fn][2] + b0, acc[fm][fn][3] + b1);
            *(float2*)(C + (size_t)r * N + c) = o0;
            *(float2*)(C + (size_t)(r + 8) * N + c) = o1;
        }
    }
}

// ---------------------------------------------------------------------------
// Fused Q/K/V projection: z=0 V (tensor, launches FIRST for overlap),
// z=1 Q (SIMT), z=2 K (SIMT). Role bodies identical to R9/R15 ->
// bitwise identical outputs; only CTA issue order differs.
// ---------------------------------------------------------------------------
__global__ __launch_bounds__(256, 2) void qkv_fused(
    const float* __restrict__ hidden,
    const float* __restrict__ wq, const float* __restrict__ bq,
    const float* __restrict__ wk, const float* __restrict__ bk,
    const float* __restrict__ wv, const float* __restrict__ bv,
    float* __restrict__ gq, float* __restrict__ gk, float* __restrict__ gv)
{
    extern __shared__ __align__(16) float dsm[];
    const int role = blockIdx.z;
    if (role == 0) {
        if (blockIdx.x >= cfg::KN / 128) return;
        mma_gemm_body(dsm, hidden, wv, bv, gv, cfg::KN, cfg::H);
    } else if (role == 1) {
        simt_gemm_body(dsm, hidden, wq, bq, gq, cfg::QN, cfg::H);
    } else {
        if (blockIdx.x >= cfg::KN / 128) return;
        simt_gemm_body(dsm, hidden, wk, bk, gk, cfg::KN, cfg::H);
    }
}

// Standalone tensor GEMM for O-projection
__global__ __launch_bounds__(256) void sgemm_mma(
    const float* __restrict__ A, const float* __restrict__ Bm,
    const float* __restrict__ bias, float* __restrict__ C,
    int N, int K)
{
    extern __shared__ __align__(16) float sm[];
    mma_gemm_body(sm, A, Bm, bias, C, N, K);
}

// ---------------------------------------------------------------------------
// RoPE (element arithmetic identical to R2..R15)
// ---------------------------------------------------------------------------
__global__ void rope_kernel(const int* __restrict__ pos)
{
    int idx = blockIdx.x * blockDim.x + threadIdx.x;
    if (idx >= cfg::MSZ * 64) return;
    const int d = idx & 63;
    const int row = idx >> 6;

    float inv_freq = (float)exp(-(double)d * (13.815510557964274 / 64.0));
    float ang = (float)pos[row] * inv_freq;
    float c, sn;
    sincosf(ang, &sn, &c);

    float* qp = g_q + (size_t)row * cfg::QN + d;
#pragma unroll
    for (int h = 0; h < cfg::NH; h++) {
        float x1 = qp[h * cfg::HD];
        float x2 = qp[h * cfg::HD + 64];
        qp[h * cfg::HD]      = x1 * c - x2 * sn;
        qp[h * cfg::HD + 64] = x2 * c + x1 * sn;
    }
    float* kp = g_k + (size_t)row * cfg::KN + d;
#pragma unroll
    for (int h = 0; h < cfg::NKV; h++) {
        float x1 = kp[h * cfg::HD];
        float x2 = kp[h * cfg::HD + 64];
        kp[h * cfg::HD]      = x1 * c - x2 * sn;
        kp[h * cfg::HD + 64] = x2 * c + x1 * sn;
    }
}

// ---------------------------------------------------------------------------
// Tiled sparse attention (exact R9/R15 kernel).
// ---------------------------------------------------------------------------
__device__ __forceinline__ unsigned f2sortable(float f) {
    unsigned u = __float_as_uint(f);
    return (u & 0x80000000u) ? ~u : (u | 0x80000000u);
}
__device__ __forceinline__ float sortable2f(unsigned v) {
    unsigned u = (v & 0x80000000u) ? (v & 0x7fffffffu) : ~v;
    return __uint_as_float(u);
}

__global__ __launch_bounds__(256, 2) void attn2_kernel(
    const float* __restrict__ q, const float* __restrict__ k,
    const float* __restrict__ v, float* __restrict__ attn)
{
    extern __shared__ __align__(16) float sm[];
    float*    ps = sm;
    unsigned* su = (unsigned*)sm;
    float*    Ks = sm + cfg::RR * cfg::SPAD;
    float*    Qs = Ks + cfg::TK * cfg::KPAD;
    __shared__ float zsh[cfg::RR];

    const int qtile = blockIdx.x, kvh = blockIdx.y, b = blockIdx.z;
    const int tid = threadIdx.x;
    const float scale = 0.08838834764831845f;

    const float* kb = k + (size_t)b * cfg::S * cfg::KN + kvh * cfg::HD;
    const float* vb = v + (size_t)b * cfg::S * cfg::KN + kvh * cfg::HD;

    float4 rv[8];
    const int prow = tid >> 5, pc4 = tid & 31;
    auto ldg_tile = [&](const float* src, int t) {
#pragma unroll
        for (int i = 0; i < 8; i++)
            rv[i] = *(const float4*)(src + (size_t)(t * cfg::TK + prow + i * 8) * cfg::KN + pc4 * 4);
    };
    auto sts_tile = [&]() {
#pragma unroll
        for (int i = 0; i < 8; i++)
            *(float4*)(Ks + (prow + i * 8) * cfg::KPAD + pc4 * 4) = rv[i];
    };

    // ---- load Q rows (16 x 128) ----
#pragma unroll
    for (int it = 0; it < 2; it++) {
        int idx = tid + it * 256;
        int r = idx >> 5, c4 = idx & 31;
        int g = r >> 3, qi = r & 7;
        int s = qtile * cfg::QT + qi, h = kvh * cfg::GROUPS + g;
        float4 val = *(const float4*)(q + (size_t)(b * cfg::S + s) * cfg::QN + h * cfg::HD + c4 * 4);
        *(float4*)(Qs + r * cfg::KPAD + c4 * 4) = val;
    }

    // ---- score pass ----
    const int sj = tid & 63, r0 = tid >> 6;
    ldg_tile(kb, 0);
#pragma unroll 1
    for (int t = 0; t < cfg::NT; t++) {
        sts_tile();
        __syncthreads();
        if (t + 1 < cfg::NT) ldg_tile(kb, t + 1);

        u64 accp[4][2];
#pragma unroll
        for (int t4 = 0; t4 < 4; t4++) { accp[t4][0] = 0ull; accp[t4][1] = 0ull; }
#pragma unroll
        for (int k4 = 0; k4 < 32; k4++) {
            float4 kv = *(const float4*)(Ks + sj * cfg::KPAD + k4 * 4);
            u64 kv01 = pack2(kv.x, kv.y), kv23 = pack2(kv.z, kv.w);
#pragma unroll
            for (int t4 = 0; t4 < 4; t4++) {
                float4 qv = *(const float4*)(Qs + (r0 + 4 * t4) * cfg::KPAD + k4 * 4);
                fma2(accp[t4][0], pack2(qv.x, qv.y), kv01);
                fma2(accp[t4][1], pack2(qv.z, qv.w), kv23);
            }
        }
#pragma unroll
        for (int t4 = 0; t4 < 4; t4++) {
            float2 u0 = unpack2(accp[t4][0]);
            float2 u1 = unpack2(accp[t4][1]);
            float sv = ((u0.x + u0.y) + (u1.x + u1.y)) * scale;
            su[(r0 + 4 * t4) * cfg::SPAD + t * cfg::TK + sj] = f2sortable(sv);
        }
        __syncthreads();
    }

    // ---- per-warp radix select (early-exit exact) + softmax weights ----
    const int lane = tid & 31, w = tid >> 5;
#pragma unroll
    for (int rr8 = 0; rr8 < 2; rr8++) {
        const int r = w + rr8 * 8;
        unsigned vals[32];
#pragma unroll
        for (int i = 0; i < 32; i++) vals[i] = su[r * cfg::SPAD + i * 32 + lane];
        unsigned mx = 0;
#pragma unroll
        for (int i = 0; i < 32; i++) mx = max(mx, vals[i]);
        mx = __reduce_max_sync(0xffffffffu, mx);
        unsigned prefix = 0u;
        for (int bit = 31; bit >= 0; bit--) {
            unsigned cand = prefix | (1u << bit);
            int c = 0;
#pragma unroll
            for (int i = 0; i < 32; i++) c += (vals[i] >= cand) ? 1 : 0;
            c = __reduce_add_sync(0xffffffffu, c);
            if (c == cfg::TOPK) {
                unsigned mn = 0xffffffffu;
#pragma unroll
                for (int i = 0; i < 32; i++)
                    if (vals[i] >= cand) mn = min(mn, vals[i]);
                prefix = __reduce_min_sync(0xffffffffu, mn);
                break;
            }
            if (c > cfg::TOPK) prefix = cand;
        }
        const float rowmax = sortable2f(mx);
        float z = 0.f;
#pragma unroll
        for (int i = 0; i < 32; i++) {
            float e = 0.f;
            if (vals[i] >= prefix) e = expf(sortable2f(vals[i]) - rowmax);
            z += e;
            ps[r * cfg::SPAD + i * 32 + lane] = e;
        }
#pragma unroll
        for (int o = 16; o; o >>= 1) z += __shfl_xor_sync(0xffffffffu, z, o);
        if (lane == 0) zsh[r] = 1.0f / z;
    }
    __syncthreads();

    // ---- AV pass on tensor mma: warp w owns dims [w*16, w*16+16) ----
    const int lr4 = lane >> 2, lk = lane & 3;
    const int dbase = w * 16;
    float accv[2][4];
#pragma unroll
    for (int i = 0; i < 2; i++)
#pragma unroll
        for (int j = 0; j < 4; j++) accv[i][j] = 0.f;

    ldg_tile(vb, 0);
#pragma unroll 1
    for (int t = 0; t < cfg::NT; t++) {
        sts_tile();
        __syncthreads();
        if (t + 1 < cfg::NT) ldg_tile(vb, t + 1);
#pragma unroll
        for (int ks = 0; ks < 8; ks++) {
            const int jb = t * cfg::TK + ks * 8 + lk;
            float p0 = ps[lr4 * cfg::SPAD + jb];
            float p1 = ps[(lr4 + 8) * cfg::SPAD + jb];
            float p2 = ps[lr4 * cfg::SPAD + jb + 4];
            float p3 = ps[(lr4 + 8) * cfg::SPAD + jb + 4];
            float h0 = tf32_rna(p0), h1 = tf32_rna(p1);
            float h2 = tf32_rna(p2), h3 = tf32_rna(p3);
            uint32_t ah[4] = {__float_as_uint(h0), __float_as_uint(h1),
                              __float_as_uint(h2), __float_as_uint(h3)};
            uint32_t al[4] = {__float_as_uint(tf32_rna(p0 - h0)),
                              __float_as_uint(tf32_rna(p1 - h1)),
                              __float_as_uint(tf32_rna(p2 - h2)),
                              __float_as_uint(tf32_rna(p3 - h3))};
            const int jl = ks * 8 + lk;
#pragma unroll
            for (int nt2 = 0; nt2 < 2; nt2++) {
                const int dn = dbase + nt2 * 8 + lr4;
                float v0 = Ks[jl * cfg::KPAD + dn];
                float v1 = Ks[(jl + 4) * cfg::KPAD + dn];
                float vh0 = tf32_rna(v0), vh1 = tf32_rna(v1);
                uint32_t bh0 = __float_as_uint(vh0);
                uint32_t bh1 = __float_as_uint(vh1);
                uint32_t bl0 = __float_as_uint(tf32_rna(v0 - vh0));
                uint32_t bl1 = __float_as_uint(tf32_rna(v1 - vh1));
                mma_tf32(accv[nt2], ah, bh0, bh1);
                mma_tf32(accv[nt2], ah, bl0, bl1);
                mma_tf32(accv[nt2], al, bh0, bh1);
            }
        }
        __syncthreads();
    }

    // ---- write out ----
    {
        const int s = qtile * cfg::QT + lr4;
        const int hA = kvh * cfg::GROUPS + 0;
        const int hB = kvh * cfg::GROUPS + 1;
        const float ziA = zsh[lr4], ziB = zsh[lr4 + 8];
        float* outb = attn + (size_t)(b * cfg::S + s) * cfg::QN;
#pragma unroll
        for (int nt2 = 0; nt2 < 2; nt2++) {
            const int c = dbase + nt2 * 8 + 2 * lk;
            *(float2*)(outb + hA * cfg::HD + c) =
                make_float2(accv[nt2][0] * ziA, accv[nt2][1] * ziA);
            *(float2*)(outb + hB * cfg::HD + c) =
                make_float2(accv[nt2][2] * ziB, accv[nt2][3] * ziB);
        }
    }
}

// ---------------------------------------------------------------------------
// Launch
// ---------------------------------------------------------------------------
extern "C" void kernel_launch(void* const* d_in, const int* in_sizes, int n_in,
                              void* d_out, int out_size)
{
    const float* hidden = (const float*)d_in[0];
    const float* wq = (const float*)d_in[1];
    const float* bq = (const float*)d_in[2];
    const float* wk = (const float*)d_in[3];
    const float* bk = (const float*)d_in[4];
    const float* wv = (const float*)d_in[5];
    const float* bv = (const float*)d_in[6];
    const float* wo = (const float*)d_in[7];
    const float* bo = (const float*)d_in[8];
    const int*  pos = (const int*)d_in[9];
    float* out = (float*)d_out;

    float *gq, *gk, *gv, *ga;
    cudaGetSymbolAddress((void**)&gq, g_q);
    cudaGetSymbolAddress((void**)&gk, g_k);
    cudaGetSymbolAddress((void**)&gv, g_v);
    cudaGetSymbolAddress((void**)&ga, g_attn);

    cudaFuncSetAttribute(qkv_fused, cudaFuncAttributeMaxDynamicSharedMemorySize,
                         tc::SMEM_TOTAL);
    cudaFuncSetAttribute(sgemm_mma, cudaFuncAttributeMaxDynamicSharedMemorySize,
                         tc::SMEM_TOTAL);
    const int attn_smem = (cfg::RR * cfg::SPAD + cfg::TK * cfg::KPAD
                           + cfg::RR * cfg::KPAD) * (int)sizeof(float);
    cudaFuncSetAttribute(attn2_kernel, cudaFuncAttributeMaxDynamicSharedMemorySize,
                         attn_smem);

    // Fused V (tensor, first) + Q (SIMT) + K (SIMT) projections — one grid
    qkv_fused<<<dim3(cfg::QN / 128, cfg::MSZ / 128, 3), 256, tc::SMEM_TOTAL>>>(
        hidden, wq, bq, wk, bk, wv, bv, gq, gk, gv);

    // RoPE
    rope_kernel<<<(cfg::MSZ * 64 + 255) / 256, 256>>>(pos);

    // Tiled sparse attention
    attn2_kernel<<<dim3(cfg::S / cfg::QT, cfg::NKV, cfg::B), 256, attn_smem>>>(
        gq, gk, gv, ga);

    // Output projection: tensor 3xTF32
    sgemm_mma<<<dim3(cfg::H / 128, cfg::MSZ / 128), 256, tc::SMEM_TOTAL>>>(
        ga, wo, bo, out, cfg::H, cfg::QN);
}

// round 17
// speedup vs baseline: 1.0259x; 1.0259x over previous
#include <cuda_runtime.h>
#include <math.h>
#include <stdint.h>

// Problem constants
namespace cfg {
constexpr int B = 2, S = 1024, H = 2048;
constexpr int NH = 16, NKV = 8, HD = 128;
constexpr int GROUPS = NH / NKV;       // 2
constexpr int TOPK = 409;              // int(0.4 * 1024)
constexpr int MSZ = B * S;             // 2048
constexpr int QN = NH * HD;            // 2048
constexpr int KN = NKV * HD;           // 1024
// attention tiling
constexpr int QT = 8;
constexpr int RR = QT * GROUPS;        // 16
constexpr int TK = 64;
constexpr int NT = S / TK;             // 16
constexpr int KPAD = 132;              // K/V tile row stride (floats)
constexpr int SPAD = 1028;             // ps/su row stride (floats)
}

// Scratch
__device__ float g_q[(size_t)cfg::MSZ * cfg::QN];
__device__ float g_k[(size_t)cfg::MSZ * cfg::KN];
__device__ float g_v[(size_t)cfg::MSZ * cfg::KN];
__device__ float g_attn[(size_t)cfg::MSZ * cfg::QN];

// ---------------------------------------------------------------------------
// Packed dual-fp32 FMA (bitwise identical to two fmaf calls)
// ---------------------------------------------------------------------------
typedef unsigned long long u64;
__device__ __forceinline__ u64 pack2(float lo, float hi) {
    u64 r;
    asm("mov.b64 %0, {%1, %2};" : "=l"(r) : "f"(lo), "f"(hi));
    return r;
}
__device__ __forceinline__ void fma2(u64& d, u64 a, u64 b) {
    asm("fma.rn.f32x2 %0, %1, %2, %0;" : "+l"(d) : "l"(a), "l"(b));
}
__device__ __forceinline__ float2 unpack2(u64 v) {
    float2 r;
    asm("mov.b64 {%0, %1}, %2;" : "=f"(r.x), "=f"(r.y) : "l"(v));
    return r;
}

// ---------------------------------------------------------------------------
// Tensor helpers
// ---------------------------------------------------------------------------
__device__ __forceinline__ float tf32_rna(float x) {
    float r;
    asm("cvt.rna.tf32.f32 %0, %1;" : "=f"(r) : "f"(x));
    return r;
}
__device__ __forceinline__ void mma_tf32(float* c, const uint32_t* a,
                                         uint32_t b0, uint32_t b1) {
    asm volatile(
        "mma.sync.aligned.m16n8k8.row.col.f32.tf32.tf32.f32 "
        "{%0,%1,%2,%3}, {%4,%5,%6,%7}, {%8,%9}, {%0,%1,%2,%3};"
        : "+f"(c[0]), "+f"(c[1]), "+f"(c[2]), "+f"(c[3])
        : "r"(a[0]), "r"(a[1]), "r"(a[2]), "r"(a[3]), "r"(b0), "r"(b1));
}

// ---------------------------------------------------------------------------
// SIMT fp32 GEMM body (double-buffered, FFMA2). Per-output FMA chain
// identical to R2..R8 -> bitwise identical results. Smem comes from caller.
// ---------------------------------------------------------------------------
__device__ __forceinline__ void simt_gemm_body(
    float* dsm, const float* __restrict__ A, const float* __restrict__ Bm,
    const float* __restrict__ bias, float* __restrict__ C, int N, int K)
{
    // layout: As[2][16][128] at dsm, Bs[2][16][128] at dsm+4096
    float* As = dsm;
    float* Bs = dsm + 4096;
    const int tid = threadIdx.x;
    const int bm = blockIdx.y * 128;
    const int bn = blockIdx.x * 128;
    const int tm = (tid >> 4) << 3;
    const int tn = (tid & 15) << 3;
    const int lr = tid >> 2;
    const int lc = (tid & 3) << 2;

    u64 acc2[8][4];
#pragma unroll
    for (int i = 0; i < 8; i++)
#pragma unroll
        for (int j = 0; j < 4; j++) acc2[i][j] = 0ull;

    const float* Ap = A + (size_t)(bm + lr) * K + lc;
    const float* Bp = Bm + (size_t)(bn + lr) * K + lc;

    float4 a0, a1, b0, b1;
    auto ldg = [&](int k0) {
        a0 = *(const float4*)(Ap + k0);
        a1 = *(const float4*)(Ap + (size_t)64 * K + k0);
        b0 = *(const float4*)(Bp + k0);
        b1 = *(const float4*)(Bp + (size_t)64 * K + k0);
    };
    auto sts = [&](int s) {
        float* as = As + s * 2048;
        float* bs = Bs + s * 2048;
        as[(lc + 0) * 128 + lr]      = a0.x; as[(lc + 1) * 128 + lr]      = a0.y;
        as[(lc + 2) * 128 + lr]      = a0.z; as[(lc + 3) * 128 + lr]      = a0.w;
        as[(lc + 0) * 128 + lr + 64] = a1.x; as[(lc + 1) * 128 + lr + 64] = a1.y;
        as[(lc + 2) * 128 + lr + 64] = a1.z; as[(lc + 3) * 128 + lr + 64] = a1.w;
        bs[(lc + 0) * 128 + lr]      = b0.x; bs[(lc + 1) * 128 + lr]      = b0.y;
        bs[(lc + 2) * 128 + lr]      = b0.z; bs[(lc + 3) * 128 + lr]      = b0.w;
        bs[(lc + 0) * 128 + lr + 64] = b1.x; bs[(lc + 1) * 128 + lr + 64] = b1.y;
        bs[(lc + 2) * 128 + lr + 64] = b1.z; bs[(lc + 3) * 128 + lr + 64] = b1.w;
    };

    ldg(0);
    sts(0);
    __syncthreads();

#pragma unroll 1
    for (int k0 = 0; k0 < K; k0 += 16) {
        const int cur = (k0 >> 4) & 1;
        if (k0 + 16 < K) ldg(k0 + 16);
        const float* as = As + cur * 2048;
        const float* bs = Bs + cur * 2048;
#pragma unroll
        for (int kk = 0; kk < 16; kk++) {
            float4 a40 = *(const float4*)&as[kk * 128 + tm];
            float4 a41 = *(const float4*)&as[kk * 128 + tm + 4];
            float4 b40 = *(const float4*)&bs[kk * 128 + tn];
            float4 b41 = *(const float4*)&bs[kk * 128 + tn + 4];
            float av[8] = {a40.x, a40.y, a40.z, a40.w, a41.x, a41.y, a41.z, a41.w};
            u64 bp[4] = {pack2(b40.x, b40.y), pack2(b40.z, b40.w),
                         pack2(b41.x, b41.y), pack2(b41.z, b41.w)};
#pragma unroll
            for (int i = 0; i < 8; i++) {
                u64 ai = pack2(av[i], av[i]);
#pragma unroll
                for (int j = 0; j < 4; j++)
                    fma2(acc2[i][j], ai, bp[j]);
            }
        }
        if (k0 + 16 < K) sts(cur ^ 1);
        __syncthreads();
    }

    float bvv[8];
#pragma unroll
    for (int j = 0; j < 8; j++) bvv[j] = bias[bn + tn + j];
#pragma unroll
    for (int i = 0; i < 8; i++) {
        float* Cp = C + (size_t)(bm + tm + i) * N + bn + tn;
#pragma unroll
        for (int j = 0; j < 4; j++) {
            float2 p = unpack2(acc2[i][j]);
            Cp[2 * j]     = p.x + bvv[2 * j];
            Cp[2 * j + 1] = p.y + bvv[2 * j + 1];
        }
    }
}

// ---------------------------------------------------------------------------
// 3-term TF32 GEMM body (smooth path). Smem from caller (needs 81920 B).
// ---------------------------------------------------------------------------
namespace tc {
constexpr int BM = 128, BN = 128, BK = 16;
constexpr int PAD = 20;
constexpr int TSZ = BM * PAD;
constexpr int STAGE = 4 * TSZ;
constexpr int SMEM_TOTAL = 2 * STAGE * 4;  // 81920 bytes
}

__device__ __forceinline__ void mma_gemm_body(
    float* sm, const float* __restrict__ A, const float* __restrict__ Bm,
    const float* __restrict__ bias, float* __restrict__ C, int N, int K)
{
    const int tid = threadIdx.x;
    const int lane = tid & 31, wid = tid >> 5;
    const int bm = blockIdx.y * tc::BM;
    const int bn = blockIdx.x * tc::BN;
    const int m0 = (wid & 3) * 32;
    const int n0 = (wid >> 2) * 64;

    float acc[2][8][4];
#pragma unroll
    for (int i = 0; i < 2; i++)
#pragma unroll
        for (int j = 0; j < 8; j++)
#pragma unroll
            for (int t = 0; t < 4; t++) acc[i][j][t] = 0.f;

    const int lrow = tid >> 2;
    const int lc4 = (tid & 3) * 4;
    float4 ra0, ra1, rb0, rb1;

    auto ldregs = [&](int kt) {
        const int k0 = kt * tc::BK;
        ra0 = *(const float4*)(A + (size_t)(bm + lrow) * K + k0 + lc4);
        ra1 = *(const float4*)(A + (size_t)(bm + lrow + 64) * K + k0 + lc4);
        rb0 = *(const float4*)(Bm + (size_t)(bn + lrow) * K + k0 + lc4);
        rb1 = *(const float4*)(Bm + (size_t)(bn + lrow + 64) * K + k0 + lc4);
    };
    auto split_store = [&](float* hi, float* lo, int row, float4 x) {
        float4 h, l;
        h.x = tf32_rna(x.x); l.x = tf32_rna(x.x - h.x);
        h.y = tf32_rna(x.y); l.y = tf32_rna(x.y - h.y);
        h.z = tf32_rna(x.z); l.z = tf32_rna(x.z - h.z);
        h.w = tf32_rna(x.w); l.w = tf32_rna(x.w - h.w);
        *(float4*)(hi + row * tc::PAD + lc4) = h;
        *(float4*)(lo + row * tc::PAD + lc4) = l;
    };
    auto stregs = [&](int s) {
        float* base = sm + s * tc::STAGE;
        split_store(base,               base + tc::TSZ,     lrow,      ra0);
        split_store(base,               base + tc::TSZ,     lrow + 64, ra1);
        split_store(base + 2 * tc::TSZ, base + 3 * tc::TSZ, lrow,      rb0);
        split_store(base + 2 * tc::TSZ, base + 3 * tc::TSZ, lrow + 64, rb1);
    };

    auto mma_stage = [&](int s) {
        const float* Ahi = sm + s * tc::STAGE;
        const float* Alo = Ahi + tc::TSZ;
        const float* Bhi = Ahi + 2 * tc::TSZ;
        const float* Blo = Ahi + 3 * tc::TSZ;
        const int lr4 = lane >> 2, lk = lane & 3;
#pragma unroll
        for (int ks = 0; ks < 2; ks++) {
            const int kb = ks * 8 + lk;
            uint32_t ah[2][4], al[2][4];
#pragma unroll
            for (int fm = 0; fm < 2; fm++) {
                const int mr = m0 + 16 * fm + lr4;
                ah[fm][0] = __float_as_uint(Ahi[mr * tc::PAD + kb]);
                ah[fm][1] = __float_as_uint(Ahi[(mr + 8) * tc::PAD + kb]);
                ah[fm][2] = __float_as_uint(Ahi[mr * tc::PAD + kb + 4]);
                ah[fm][3] = __float_as_uint(Ahi[(mr + 8) * tc::PAD + kb + 4]);
                al[fm][0] = __float_as_uint(Alo[mr * tc::PAD + kb]);
                al[fm][1] = __float_as_uint(Alo[(mr + 8) * tc::PAD + kb]);
                al[fm][2] = __float_as_uint(Alo[mr * tc::PAD + kb + 4]);
                al[fm][3] = __float_as_uint(Alo[(mr + 8) * tc::PAD + kb + 4]);
            }
#pragma unroll
            for (int fn = 0; fn < 8; fn++) {
                const int nr = n0 + 8 * fn + lr4;
                uint32_t bh0 = __float_as_uint(Bhi[nr * tc::PAD + kb]);
                uint32_t bh1 = __float_as_uint(Bhi[nr * tc::PAD + kb + 4]);
                uint32_t bl0 = __float_as_uint(Blo[nr * tc::PAD + kb]);
                uint32_t bl1 = __float_as_uint(Blo[nr * tc::PAD + kb + 4]);
#pragma unroll
                for (int fm = 0; fm < 2; fm++) {
                    mma_tf32(acc[fm][fn], ah[fm], bh0, bh1);
                    mma_tf32(acc[fm][fn], ah[fm], bl0, bl1);
                    mma_tf32(acc[fm][fn], al[fm], bh0, bh1);
                }
            }
        }
    };

    const int NK = K / tc::BK;
    ldregs(0);
    stregs(0);
    __syncthreads();
#pragma unroll 1
    for (int kt = 0; kt < NK; kt++) {
        const int cur = kt & 1;
        if (kt + 1 < NK) ldregs(kt + 1);
        mma_stage(cur);
        if (kt + 1 < NK) stregs(cur ^ 1);
        __syncthreads();
    }

    const int lr4 = lane >> 2, lc2 = 2 * (lane & 3);
#pragma unroll
    for (int fm = 0; fm < 2; fm++) {
#pragma unroll
        for (int fn = 0; fn < 8; fn++) {
            const int r = bm + m0 + 16 * fm + lr4;
            const int c = bn + n0 + 8 * fn + lc2;
            const float b0 = bias[c], b1 = bias[c + 1];
            float2 o0 = make_float2(acc[fm][fn][0] + b0, acc[fm][fn][1] + b1);
            float2 o1 = make_float2(acc[fm][fn][2] + b0, acc[fm][fn][3] + b1);
            *(float2*)(C + (size_t)r * N + c) = o0;
            *(float2*)(C + (size_t)(r + 8) * N + c) = o1;
        }
    }
}

// ---------------------------------------------------------------------------
// Fused Q/K/V projection: z=0 Q (SIMT), z=1 K (SIMT), z=2 V (tensor).
// One grid -> V's tensor work overlaps the fp32-bound Q/K, and wave fill
// improves vs three serial launches.
// ---------------------------------------------------------------------------
__global__ __launch_bounds__(256, 2) void qkv_fused(
    const float* __restrict__ hidden,
    const float* __restrict__ wq, const float* __restrict__ bq,
    const float* __restrict__ wk, const float* __restrict__ bk,
    const float* __restrict__ wv, const float* __restrict__ bv,
    float* __restrict__ gq, float* __restrict__ gk, float* __restrict__ gv)
{
    extern __shared__ __align__(16) float dsm[];
    const int role = blockIdx.z;
    if (role == 0) {
        simt_gemm_body(dsm, hidden, wq, bq, gq, cfg::QN, cfg::H);
    } else if (role == 1) {
        if (blockIdx.x >= cfg::KN / 128) return;
        simt_gemm_body(dsm, hidden, wk, bk, gk, cfg::KN, cfg::H);
    } else {
        if (blockIdx.x >= cfg::KN / 128) return;
        mma_gemm_body(dsm, hidden, wv, bv, gv, cfg::KN, cfg::H);
    }
}

// Standalone tensor GEMM for O-projection
__global__ __launch_bounds__(256) void sgemm_mma(
    const float* __restrict__ A, const float* __restrict__ Bm,
    const float* __restrict__ bias, float* __restrict__ C,
    int N, int K)
{
    extern __shared__ __align__(16) float sm[];
    mma_gemm_body(sm, A, Bm, bias, C, N, K);
}

// ---------------------------------------------------------------------------
// RoPE (element arithmetic identical to R2/R5)
// ---------------------------------------------------------------------------
__global__ void rope_kernel(const int* __restrict__ pos)
{
    int idx = blockIdx.x * blockDim.x + threadIdx.x;
    if (idx >= cfg::MSZ * 64) return;
    const int d = idx & 63;
    const int row = idx >> 6;

    float inv_freq = (float)exp(-(double)d * (13.815510557964274 / 64.0));
    float ang = (float)pos[row] * inv_freq;
    float c, sn;
    sincosf(ang, &sn, &c);

    float* qp = g_q + (size_t)row * cfg::QN + d;
#pragma unroll
    for (int h = 0; h < cfg::NH; h++) {
        float x1 = qp[h * cfg::HD];
        float x2 = qp[h * cfg::HD + 64];
        qp[h * cfg::HD]      = x1 * c - x2 * sn;
        qp[h * cfg::HD + 64] = x2 * c + x1 * sn;
    }
    float* kp = g_k + (size_t)row * cfg::KN + d;
#pragma unroll
    for (int h = 0; h < cfg::NKV; h++) {
        float x1 = kp[h * cfg::HD];
        float x2 = kp[h * cfg::HD + 64];
        kp[h * cfg::HD]      = x1 * c - x2 * sn;
        kp[h * cfg::HD + 64] = x2 * c + x1 * sn;
    }
}

// ---------------------------------------------------------------------------
// Tiled sparse attention (score arithmetic bitwise = R2..R8; radix select
// with provably-identical early exit; tensor AV).
// ---------------------------------------------------------------------------
__device__ __forceinline__ unsigned f2sortable(float f) {
    unsigned u = __float_as_uint(f);
    return (u & 0x80000000u) ? ~u : (u | 0x80000000u);
}
__device__ __forceinline__ float sortable2f(unsigned v) {
    unsigned u = (v & 0x80000000u) ? (v & 0x7fffffffu) : ~v;
    return __uint_as_float(u);
}

__global__ __launch_bounds__(256, 2) void attn2_kernel(
    const float* __restrict__ q, const float* __restrict__ k,
    const float* __restrict__ v, float* __restrict__ attn)
{
    extern __shared__ __align__(16) float sm[];
    float*    ps = sm;                          // [RR][SPAD] weights
    unsigned* su = (unsigned*)sm;               // same storage: sortable scores
    float*    Ks = sm + cfg::RR * cfg::SPAD;    // [TK][KPAD] K then V tiles
    float*    Qs = Ks + cfg::TK * cfg::KPAD;    // [RR][KPAD]
    __shared__ float zsh[cfg::RR];

    const int qtile = blockIdx.x, kvh = blockIdx.y, b = blockIdx.z;
    const int tid = threadIdx.x;
    const float scale = 0.08838834764831845f;

    const float* kb = k + (size_t)b * cfg::S * cfg::KN + kvh * cfg::HD;
    const float* vb = v + (size_t)b * cfg::S * cfg::KN + kvh * cfg::HD;

    // tile loader state (register prefetch)
    float4 rv[8];
    const int prow = tid >> 5, pc4 = tid & 31;
    auto ldg_tile = [&](const float* src, int t) {
#pragma unroll
        for (int i = 0; i < 8; i++)
            rv[i] = *(const float4*)(src + (size_t)(t * cfg::TK + prow + i * 8) * cfg::KN + pc4 * 4);
    };
    auto sts_tile = [&]() {
#pragma unroll
        for (int i = 0; i < 8; i++)
            *(float4*)(Ks + (prow + i * 8) * cfg::KPAD + pc4 * 4) = rv[i];
    };

    // ---- load Q rows (16 x 128) ----
#pragma unroll
    for (int it = 0; it < 2; it++) {
        int idx = tid + it * 256;
        int r = idx >> 5, c4 = idx & 31;
        int g = r >> 3, qi = r & 7;
        int s = qtile * cfg::QT + qi, h = kvh * cfg::GROUPS + g;
        float4 val = *(const float4*)(q + (size_t)(b * cfg::S + s) * cfg::QN + h * cfg::HD + c4 * 4);
        *(float4*)(Qs + r * cfg::KPAD + c4 * 4) = val;
    }

    // ---- score pass ----
    const int sj = tid & 63, r0 = tid >> 6;
    ldg_tile(kb, 0);
#pragma unroll 1
    for (int t = 0; t < cfg::NT; t++) {
        sts_tile();
        __syncthreads();
        if (t + 1 < cfg::NT) ldg_tile(kb, t + 1);

        u64 accp[4][2];
#pragma unroll
        for (int t4 = 0; t4 < 4; t4++) { accp[t4][0] = 0ull; accp[t4][1] = 0ull; }
#pragma unroll
        for (int k4 = 0; k4 < 32; k4++) {
            float4 kv = *(const float4*)(Ks + sj * cfg::KPAD + k4 * 4);
            u64 kv01 = pack2(kv.x, kv.y), kv23 = pack2(kv.z, kv.w);
#pragma unroll
            for (int t4 = 0; t4 < 4; t4++) {
                float4 qv = *(const float4*)(Qs + (r0 + 4 * t4) * cfg::KPAD + k4 * 4);
                fma2(accp[t4][0], pack2(qv.x, qv.y), kv01);
                fma2(accp[t4][1], pack2(qv.z, qv.w), kv23);
            }
        }
#pragma unroll
        for (int t4 = 0; t4 < 4; t4++) {
            float2 u0 = unpack2(accp[t4][0]);
            float2 u1 = unpack2(accp[t4][1]);
            float sv = ((u0.x + u0.y) + (u1.x + u1.y)) * scale;
            su[(r0 + 4 * t4) * cfg::SPAD + t * cfg::TK + sj] = f2sortable(sv);
        }
        __syncthreads();
    }

    // ---- per-warp radix select (early-exit exact) + softmax weights ----
    const int lane = tid & 31, w = tid >> 5;
#pragma unroll
    for (int rr8 = 0; rr8 < 2; rr8++) {
        const int r = w + rr8 * 8;
        unsigned vals[32];
#pragma unroll
        for (int i = 0; i < 32; i++) vals[i] = su[r * cfg::SPAD + i * 32 + lane];
        unsigned mx = 0;
#pragma unroll
        for (int i = 0; i < 32; i++) mx = max(mx, vals[i]);
        mx = __reduce_max_sync(0xffffffffu, mx);
        unsigned prefix = 0u;
        for (int bit = 31; bit >= 0; bit--) {
            unsigned cand = prefix | (1u << bit);
            int c = 0;
#pragma unroll
            for (int i = 0; i < 32; i++) c += (vals[i] >= cand) ? 1 : 0;
            c = __reduce_add_sync(0xffffffffu, c);
            if (c == cfg::TOPK) {
                // exactly TOPK values >= cand: k-th largest == min of that set.
                // Identical threshold bits to completing all remaining passes.
                unsigned mn = 0xffffffffu;
#pragma unroll
                for (int i = 0; i < 32; i++)
                    if (vals[i] >= cand) mn = min(mn, vals[i]);
                prefix = __reduce_min_sync(0xffffffffu, mn);
                break;
            }
            if (c > cfg::TOPK) prefix = cand;
        }
        const float rowmax = sortable2f(mx);
        float z = 0.f;
#pragma unroll
        for (int i = 0; i < 32; i++) {
            float e = 0.f;
            if (vals[i] >= prefix) e = expf(sortable2f(vals[i]) - rowmax);
            z += e;
            ps[r * cfg::SPAD + i * 32 + lane] = e;
        }
#pragma unroll
        for (int o = 16; o; o >>= 1) z += __shfl_xor_sync(0xffffffffu, z, o);
        if (lane == 0) zsh[r] = 1.0f / z;
    }
    __syncthreads();

    // ---- AV pass on tensor mma: warp w owns dims [w*16, w*16+16) ----
    const int lr4 = lane >> 2, lk = lane & 3;
    const int dbase = w * 16;
    float accv[2][4];
#pragma unroll
    for (int i = 0; i < 2; i++)
#pragma unroll
        for (int j = 0; j < 4; j++) accv[i][j] = 0.f;

    ldg_tile(vb, 0);
#pragma unroll 1
    for (int t = 0; t < cfg::NT; t++) {
        sts_tile();
        __syncthreads();
        if (t + 1 < cfg::NT) ldg_tile(vb, t + 1);
#pragma unroll
        for (int ks = 0; ks < 8; ks++) {
            const int jb = t * cfg::TK + ks * 8 + lk;
            float p0 = ps[lr4 * cfg::SPAD + jb];
            float p1 = ps[(lr4 + 8) * cfg::SPAD + jb];
            float p2 = ps[lr4 * cfg::SPAD + jb + 4];
            float p3 = ps[(lr4 + 8) * cfg::SPAD + jb + 4];
            float h0 = tf32_rna(p0), h1 = tf32_rna(p1);
            float h2 = tf32_rna(p2), h3 = tf32_rna(p3);
            uint32_t ah[4] = {__float_as_uint(h0), __float_as_uint(h1),
                              __float_as_uint(h2), __float_as_uint(h3)};
            uint32_t al[4] = {__float_as_uint(tf32_rna(p0 - h0)),
                              __float_as_uint(tf32_rna(p1 - h1)),
                              __float_as_uint(tf32_rna(p2 - h2)),
                              __float_as_uint(tf32_rna(p3 - h3))};
            const int jl = ks * 8 + lk;
#pragma unroll
            for (int nt2 = 0; nt2 < 2; nt2++) {
                const int dn = dbase + nt2 * 8 + lr4;
                float v0 = Ks[jl * cfg::KPAD + dn];
                float v1 = Ks[(jl + 4) * cfg::KPAD + dn];
                float vh0 = tf32_rna(v0), vh1 = tf32_rna(v1);
                uint32_t bh0 = __float_as_uint(vh0);
                uint32_t bh1 = __float_as_uint(vh1);
                uint32_t bl0 = __float_as_uint(tf32_rna(v0 - vh0));
                uint32_t bl1 = __float_as_uint(tf32_rna(v1 - vh1));
                mma_tf32(accv[nt2], ah, bh0, bh1);
                mma_tf32(accv[nt2], ah, bl0, bl1);
                mma_tf32(accv[nt2], al, bh0, bh1);
            }
        }
        __syncthreads();
    }

    // ---- write out ----
    {
        const int s = qtile * cfg::QT + lr4;
        const int hA = kvh * cfg::GROUPS + 0;
        const int hB = kvh * cfg::GROUPS + 1;
        const float ziA = zsh[lr4], ziB = zsh[lr4 + 8];
        float* outb = attn + (size_t)(b * cfg::S + s) * cfg::QN;
#pragma unroll
        for (int nt2 = 0; nt2 < 2; nt2++) {
            const int c = dbase + nt2 * 8 + 2 * lk;
            *(float2*)(outb + hA * cfg::HD + c) =
                make_float2(accv[nt2][0] * ziA, accv[nt2][1] * ziA);
            *(float2*)(outb + hB * cfg::HD + c) =
                make_float2(accv[nt2][2] * ziB, accv[nt2][3] * ziB);
        }
    }
}

// ---------------------------------------------------------------------------
// Launch
// ---------------------------------------------------------------------------
extern "C" void kernel_launch(void* const* d_in, const int* in_sizes, int n_in,
                              void* d_out, int out_size)
{
    const float* hidden = (const float*)d_in[0];
    const float* wq = (const float*)d_in[1];
    const float* bq = (const float*)d_in[2];
    const float* wk = (const float*)d_in[3];
    const float* bk = (const float*)d_in[4];
    const float* wv = (const float*)d_in[5];
    const float* bv = (const float*)d_in[6];
    const float* wo = (const float*)d_in[7];
    const float* bo = (const float*)d_in[8];
    const int*  pos = (const int*)d_in[9];
    float* out = (float*)d_out;

    float *gq, *gk, *gv, *ga;
    cudaGetSymbolAddress((void**)&gq, g_q);
    cudaGetSymbolAddress((void**)&gk, g_k);
    cudaGetSymbolAddress((void**)&gv, g_v);
    cudaGetSymbolAddress((void**)&ga, g_attn);

    cudaFuncSetAttribute(qkv_fused, cudaFuncAttributeMaxDynamicSharedMemorySize,
                         tc::SMEM_TOTAL);
    cudaFuncSetAttribute(sgemm_mma, cudaFuncAttributeMaxDynamicSharedMemorySize,
                         tc::SMEM_TOTAL);
    const int attn_smem = (cfg::RR * cfg::SPAD + cfg::TK * cfg::KPAD
                           + cfg::RR * cfg::KPAD) * (int)sizeof(float);
    cudaFuncSetAttribute(attn2_kernel, cudaFuncAttributeMaxDynamicSharedMemorySize,
                         attn_smem);

    // Fused Q (SIMT) + K (SIMT) + V (tensor) projections — one grid
    qkv_fused<<<dim3(cfg::QN / 128, cfg::MSZ / 128, 3), 256, tc::SMEM_TOTAL>>>(
        hidden, wq, bq, wk, bk, wv, bv, gq, gk, gv);

    // RoPE
    rope_kernel<<<(cfg::MSZ * 64 + 255) / 256, 256>>>(pos);

    // Tiled sparse attention
    attn2_kernel<<<dim3(cfg::S / cfg::QT, cfg::NKV, cfg::B), 256, attn_smem>>>(
        gq, gk, gv, ga);

    // Output projection: tensor 3xTF32
    sgemm_mma<<<dim3(cfg::H / 128, cfg::MSZ / 128), 256, tc::SMEM_TOTAL>>>(
        ga, wo, bo, out, cfg::H, cfg::QN);
}